// round 14
// baseline (speedup 1.0000x reference)
#include <cuda_runtime.h>
#include <cuda_bf16.h>
#include <cstdint>

#define EMB    256
#define K1     512
#define PAIRS  15
#define M_TOT  16384
#define KF     3840            // PAIRS*EMB

__constant__ int c_i[PAIRS] = {0,0,0,0,0,1,1,1,1,2,2,2,3,3,4};
__constant__ int c_j[PAIRS] = {1,2,3,4,5,2,3,4,5,3,4,5,4,5,5};

// Scratch (device globals: allocation-guard safe)
__device__ __nv_bfloat16 g_Wphi[(size_t)PAIRS * EMB * K1];   // W_pair^T hi  [p][n][k]
__device__ __nv_bfloat16 g_Wplo[(size_t)PAIRS * EMB * K1];   // W_pair^T lo
__device__ __nv_bfloat16 g_Wfhi[(size_t)EMB * KF];           // W_final^T hi [n][k]
__device__ __nv_bfloat16 g_Wflo[(size_t)EMB * KF];           // W_final^T lo
__device__ __nv_bfloat16 g_Hhi[(size_t)PAIRS * M_TOT * EMB]; // h hi [p][m][d]
__device__ __nv_bfloat16 g_Hlo[(size_t)PAIRS * M_TOT * EMB]; // h lo

__device__ __forceinline__ bool pair_active(const int* __restrict__ NAS, int p) {
    const int i = c_i[p], j = c_j[p];
    const int ni = (i < 2) ? 1 : NAS[i];
    const int nj = (j < 2) ? 1 : NAS[j];
    return (ni != 0) && (nj != 0);
}

__device__ __forceinline__ float tanh_fast(float x) {
    float y; asm("tanh.approx.f32 %0, %1;" : "=f"(y) : "f"(x)); return y;
}
__device__ __forceinline__ uint32_t s2u(const void* p) {
    uint32_t a;
    asm("{ .reg .u64 t; cvta.to.shared.u64 t, %1; cvt.u32.u64 %0, t; }" : "=r"(a) : "l"(p));
    return a;
}
// pack (x,y) -> bf16x2 with x in low half (memory order [x,y])
__device__ __forceinline__ uint32_t packbf(float x, float y) {
    uint32_t r; asm("cvt.rn.bf16x2.f32 %0, %1, %2;" : "=r"(r) : "f"(y), "f"(x));
    return r;
}
// residual pair: lo = val - float(hi)
__device__ __forceinline__ uint32_t lopair(uint32_t hp, float x, float y) {
    float hx = __uint_as_float(hp << 16);
    float hy = __uint_as_float(hp & 0xffff0000u);
    return packbf(x - hx, y - hy);
}
__device__ __forceinline__ void ldsm4(uint32_t* r, uint32_t addr) {
    asm volatile("ldmatrix.sync.aligned.m8n8.x4.shared.b16 {%0,%1,%2,%3}, [%4];"
                 : "=r"(r[0]), "=r"(r[1]), "=r"(r[2]), "=r"(r[3]) : "r"(addr));
}
__device__ __forceinline__ void mma16816(float* d, const uint32_t* a, uint32_t b0, uint32_t b1) {
    asm volatile("mma.sync.aligned.m16n8k16.row.col.f32.bf16.bf16.f32 "
                 "{%0,%1,%2,%3}, {%4,%5,%6,%7}, {%8,%9}, {%0,%1,%2,%3};"
                 : "+f"(d[0]), "+f"(d[1]), "+f"(d[2]), "+f"(d[3])
                 : "r"(a[0]), "r"(a[1]), "r"(a[2]), "r"(a[3]), "r"(b0), "r"(b1));
}
__device__ __forceinline__ void cpa16(uint32_t dst, const void* src) {
    asm volatile("cp.async.cg.shared.global [%0], [%1], 16;" :: "r"(dst), "l"(src));
}
#define CP_COMMIT() asm volatile("cp.async.commit_group;" ::: "memory")
#define CP_WAIT0()  asm volatile("cp.async.wait_group 0;" ::: "memory")

// SMEM layout: bias[128]f at 0, stages at 1024. Stage: AHI|ALO|BHI|BLO 16KB each.
#define ST_A_HI 0
#define ST_A_LO 16384
#define ST_B_HI 32768
#define ST_B_LO 49152
#define STAGE   65536
#define SM_STG  1024
#define SMEM_BYTES (SM_STG + 2 * STAGE)   // 132096

#define NTHREADS 512

// smem tile byte offset for (row, 16B-chunk u): 128B rows, XOR swizzle
__device__ __forceinline__ uint32_t swoff(int row, int u) {
    return (uint32_t)(row * 128 + ((u ^ (row & 7)) << 4));
}

// ---------------- shared compute: one BK=64 stage of split-bf16 MMA ----------
// 16 warps: warp tile 32(m) x 32(n). acc[2][4][4]: [mi][colgrp j][d]
__device__ __forceinline__ void stage_mma(uint32_t stb, int warp_m, int warp_n,
                                          int lane, float acc[2][4][4]) {
    const int l15 = lane & 15, lh = lane >> 4;
    uint32_t aoff[2], boff[2];
    int asw[2], bsw[2];
    #pragma unroll
    for (int mi = 0; mi < 2; mi++) {
        int r = warp_m * 32 + mi * 16 + l15;
        aoff[mi] = r * 128; asw[mi] = r & 7;
    }
    #pragma unroll
    for (int ng = 0; ng < 2; ng++) {
        int r = warp_n * 32 + ng * 16 + l15;
        boff[ng] = r * 128; bsw[ng] = r & 7;
    }
    #pragma unroll
    for (int kk = 0; kk < 4; kk++) {
        const int ch = kk * 2 + lh;
        uint32_t ah[2][4], al[2][4];
        #pragma unroll
        for (int mi = 0; mi < 2; mi++) {
            ldsm4(ah[mi], stb + ST_A_HI + aoff[mi] + (((ch ^ asw[mi]) & 7) << 4));
            ldsm4(al[mi], stb + ST_A_LO + aoff[mi] + (((ch ^ asw[mi]) & 7) << 4));
        }
        #pragma unroll
        for (int ng = 0; ng < 2; ng++) {
            uint32_t bh[4], bl[4];
            ldsm4(bh, stb + ST_B_HI + boff[ng] + (((ch ^ bsw[ng]) & 7) << 4));
            ldsm4(bl, stb + ST_B_LO + boff[ng] + (((ch ^ bsw[ng]) & 7) << 4));
            #pragma unroll
            for (int mi = 0; mi < 2; mi++) {
                mma16816(acc[mi][ng * 2 + 0], ah[mi], bh[0], bh[2]);
                mma16816(acc[mi][ng * 2 + 0], ah[mi], bl[0], bl[2]);
                mma16816(acc[mi][ng * 2 + 0], al[mi], bh[0], bh[2]);
                mma16816(acc[mi][ng * 2 + 1], ah[mi], bh[1], bh[3]);
                mma16816(acc[mi][ng * 2 + 1], ah[mi], bl[1], bl[3]);
                mma16816(acc[mi][ng * 2 + 1], al[mi], bh[1], bh[3]);
            }
        }
    }
}

// ---------------------------------------------------------------------------
// Prep: transpose + bf16-split weights
// ---------------------------------------------------------------------------
__global__ void prep_wp(const float* __restrict__ Wp, const int* __restrict__ NAS) {
    const int p = blockIdx.z;
    if (!pair_active(NAS, p)) return;
    __shared__ float t[64][65];
    const int k0 = blockIdx.x * 64, n0 = blockIdx.y * 64;
    const int tid = threadIdx.x;
    #pragma unroll
    for (int i = 0; i < 16; i++) {
        int idx = i * 256 + tid; int r = idx >> 6, c = idx & 63;
        t[r][c] = Wp[((size_t)p * K1 + k0 + r) * EMB + n0 + c];
    }
    __syncthreads();
    #pragma unroll
    for (int i = 0; i < 16; i++) {
        int idx = i * 256 + tid; int r = idx >> 6, c = idx & 63;
        float x = t[c][r];
        __nv_bfloat16 h = __float2bfloat16(x);
        size_t o = ((size_t)p * EMB + n0 + r) * K1 + k0 + c;
        g_Wphi[o] = h;
        g_Wplo[o] = __float2bfloat16(x - __bfloat162float(h));
    }
}
__global__ void prep_wf(const float* __restrict__ Wf, const int* __restrict__ NAS) {
    const int k0 = blockIdx.x * 64;
    if (!pair_active(NAS, k0 >> 8)) return;
    __shared__ float t[64][65];
    const int n0 = blockIdx.y * 64;
    const int tid = threadIdx.x;
    #pragma unroll
    for (int i = 0; i < 16; i++) {
        int idx = i * 256 + tid; int r = idx >> 6, c = idx & 63;
        t[r][c] = Wf[(size_t)(k0 + r) * EMB + n0 + c];
    }
    __syncthreads();
    #pragma unroll
    for (int i = 0; i < 16; i++) {
        int idx = i * 256 + tid; int r = idx >> 6, c = idx & 63;
        float x = t[c][r];
        __nv_bfloat16 h = __float2bfloat16(x);
        size_t o = (size_t)(n0 + r) * KF + k0 + c;
        g_Wfhi[o] = h;
        g_Wflo[o] = __float2bfloat16(x - __bfloat162float(h));
    }
}

// ---------------------------------------------------------------------------
// GEMM1: h[p] = tanh([f_i|f_j] @ W_p + b_p)   (HMMA, split-bf16 3-pass)
// grid: (128 Mtiles * 2 Ntiles, PAIRS), 512 threads / 16 warps
// ---------------------------------------------------------------------------
__global__ __launch_bounds__(NTHREADS, 1)
void k_pair_mma(const float* __restrict__ feat, const float* __restrict__ bp,
                const int* __restrict__ NAS)
{
    extern __shared__ char smem[];
    const int p = blockIdx.y;
    if (!pair_active(NAS, p)) return;
    const int tid = threadIdx.x, lane = tid & 31, wid = tid >> 5;
    const int warp_m = wid & 3, warp_n = wid >> 2;
    const int bm = (blockIdx.x >> 1) * 128, bn = (blockIdx.x & 1) * 128;
    const uint32_t sb = s2u(smem);
    float* bias_s = (float*)smem;
    if (tid < 32) ((float4*)bias_s)[tid] = ((const float4*)(bp + p * EMB + bn))[tid];

    const __nv_bfloat16* WH = g_Wphi + ((size_t)p * EMB + bn) * K1;
    const __nv_bfloat16* WL = g_Wplo + ((size_t)p * EMB + bn) * K1;

    float acc[2][4][4];
    #pragma unroll
    for (int a = 0; a < 2; a++)
        #pragma unroll
        for (int b = 0; b < 4; b++)
            #pragma unroll
            for (int c = 0; c < 4; c++) acc[a][b][c] = 0.f;

    const int NT = K1 / 64;   // 8
    float4 av[2][2];

    auto issueB = [&](int t, int buf) {
        const int k0 = t * 64;
        #pragma unroll
        for (int it = 0; it < 2; it++) {
            int c = it * NTHREADS + tid; int row = c >> 3, u = c & 7;
            uint32_t d = sb + SM_STG + buf * STAGE + swoff(row, u);
            cpa16(d + ST_B_HI, WH + (size_t)row * K1 + k0 + u * 8);
            cpa16(d + ST_B_LO, WL + (size_t)row * K1 + k0 + u * 8);
        }
    };
    auto ldgA = [&](int t) {
        const int k0 = t * 64;
        const int f  = (k0 < EMB) ? c_i[p] : c_j[p];
        const float* A = feat + ((size_t)f * M_TOT + bm) * EMB + (k0 & (EMB - 1));
        #pragma unroll
        for (int it = 0; it < 2; it++) {
            int c = it * NTHREADS + tid; int row = c >> 3, u = c & 7;
            av[it][0] = *reinterpret_cast<const float4*>(A + (size_t)row * EMB + u * 8);
            av[it][1] = *reinterpret_cast<const float4*>(A + (size_t)row * EMB + u * 8 + 4);
        }
    };
    auto stsA = [&](int buf) {
        #pragma unroll
        for (int it = 0; it < 2; it++) {
            int c = it * NTHREADS + tid; int row = c >> 3, u = c & 7;
            uint4 hq, lq;
            hq.x = packbf(av[it][0].x, av[it][0].y); lq.x = lopair(hq.x, av[it][0].x, av[it][0].y);
            hq.y = packbf(av[it][0].z, av[it][0].w); lq.y = lopair(hq.y, av[it][0].z, av[it][0].w);
            hq.z = packbf(av[it][1].x, av[it][1].y); lq.z = lopair(hq.z, av[it][1].x, av[it][1].y);
            hq.w = packbf(av[it][1].z, av[it][1].w); lq.w = lopair(hq.w, av[it][1].z, av[it][1].w);
            char* base = smem + SM_STG + buf * STAGE + swoff(row, u);
            *reinterpret_cast<uint4*>(base + ST_A_HI) = hq;
            *reinterpret_cast<uint4*>(base + ST_A_LO) = lq;
        }
    };

    // prologue
    issueB(0, 0); CP_COMMIT();
    ldgA(0); stsA(0);
    CP_WAIT0(); __syncthreads();

    for (int t = 0; t < NT; t++) {
        const int buf = t & 1;
        if (t + 1 < NT) { issueB(t + 1, buf ^ 1); CP_COMMIT(); ldgA(t + 1); }
        stage_mma(sb + SM_STG + buf * STAGE, warp_m, warp_n, lane, acc);
        if (t + 1 < NT) stsA(buf ^ 1);
        CP_WAIT0(); __syncthreads();
    }

    // epilogue: bias + tanh -> hi/lo bf16 in g_H
    const int r0 = lane >> 2, c2 = (lane & 3) * 2;
    #pragma unroll
    for (int mi = 0; mi < 2; mi++)
        #pragma unroll
        for (int hf = 0; hf < 2; hf++) {
            const int m = bm + warp_m * 32 + mi * 16 + r0 + hf * 8;
            const size_t rb = ((size_t)p * M_TOT + m) * EMB + bn + warp_n * 32;
            #pragma unroll
            for (int j = 0; j < 4; j++) {
                const int col = j * 8 + c2;
                float x0 = tanh_fast(acc[mi][j][hf * 2 + 0] + bias_s[warp_n * 32 + col]);
                float x1 = tanh_fast(acc[mi][j][hf * 2 + 1] + bias_s[warp_n * 32 + col + 1]);
                uint32_t hp = packbf(x0, x1);
                uint32_t lp = lopair(hp, x0, x1);
                *reinterpret_cast<uint32_t*>(g_Hhi + rb + col) = hp;
                *reinterpret_cast<uint32_t*>(g_Hlo + rb + col) = lp;
            }
        }
}

// ---------------------------------------------------------------------------
// GEMM2: out = h_flat @ W_final + b_final (active pairs only)
// grid: 128 Mtiles * 2 Ntiles, 512 threads / 16 warps
// ---------------------------------------------------------------------------
__global__ __launch_bounds__(NTHREADS, 1)
void k_final_mma(const float* __restrict__ bf, const int* __restrict__ NAS,
                 float* __restrict__ out)
{
    extern __shared__ char smem[];
    const int tid = threadIdx.x, lane = tid & 31, wid = tid >> 5;
    const int warp_m = wid & 3, warp_n = wid >> 2;
    const int bm = (blockIdx.x >> 1) * 128, bn = (blockIdx.x & 1) * 128;
    const uint32_t sb = s2u(smem);
    float* bias_s = (float*)smem;
    if (tid < 32) ((float4*)bias_s)[tid] = ((const float4*)(bf + bn))[tid];

    int act[PAIRS]; int nact = 0;
    #pragma unroll
    for (int p = 0; p < PAIRS; p++)
        if (pair_active(NAS, p)) act[nact++] = p;
    const int NT = nact * 4;

    float acc[2][4][4];
    #pragma unroll
    for (int a = 0; a < 2; a++)
        #pragma unroll
        for (int b = 0; b < 4; b++)
            #pragma unroll
            for (int c = 0; c < 4; c++) acc[a][b][c] = 0.f;

    auto issue = [&](int t, int buf) {
        const int p  = act[t >> 2];
        const int k0 = (t & 3) * 64;
        const __nv_bfloat16* HH = g_Hhi + ((size_t)p * M_TOT + bm) * EMB + k0;
        const __nv_bfloat16* HL = g_Hlo + ((size_t)p * M_TOT + bm) * EMB + k0;
        const __nv_bfloat16* WH = g_Wfhi + (size_t)bn * KF + p * EMB + k0;
        const __nv_bfloat16* WL = g_Wflo + (size_t)bn * KF + p * EMB + k0;
        #pragma unroll
        for (int it = 0; it < 2; it++) {
            int c = it * NTHREADS + tid; int row = c >> 3, u = c & 7;
            uint32_t d = sb + SM_STG + buf * STAGE + swoff(row, u);
            cpa16(d + ST_A_HI, HH + (size_t)row * EMB + u * 8);
            cpa16(d + ST_A_LO, HL + (size_t)row * EMB + u * 8);
            cpa16(d + ST_B_HI, WH + (size_t)row * KF + u * 8);
            cpa16(d + ST_B_LO, WL + (size_t)row * KF + u * 8);
        }
    };

    issue(0, 0); CP_COMMIT();
    CP_WAIT0(); __syncthreads();

    for (int t = 0; t < NT; t++) {
        const int buf = t & 1;
        if (t + 1 < NT) { issue(t + 1, buf ^ 1); CP_COMMIT(); }
        stage_mma(sb + SM_STG + buf * STAGE, warp_m, warp_n, lane, acc);
        CP_WAIT0(); __syncthreads();
    }

    const int r0 = lane >> 2, c2 = (lane & 3) * 2;
    #pragma unroll
    for (int mi = 0; mi < 2; mi++)
        #pragma unroll
        for (int hf = 0; hf < 2; hf++) {
            const int m = bm + warp_m * 32 + mi * 16 + r0 + hf * 8;
            float* ob = out + (size_t)m * EMB + bn + warp_n * 32;
            #pragma unroll
            for (int j = 0; j < 4; j++) {
                const int col = j * 8 + c2;
                float2 v;
                v.x = acc[mi][j][hf * 2 + 0] + bias_s[warp_n * 32 + col];
                v.y = acc[mi][j][hf * 2 + 1] + bias_s[warp_n * 32 + col + 1];
                *reinterpret_cast<float2*>(ob + col) = v;
            }
        }
}

extern "C" void kernel_launch(void* const* d_in, const int* in_sizes, int n_in,
                              void* d_out, int out_size)
{
    const float* feat = (const float*)d_in[0];   // [6, 32, 512, 256]
    const float* Wp   = (const float*)d_in[1];   // [15, 512, 256]
    const float* bp   = (const float*)d_in[2];   // [15, 256]
    const float* Wf   = (const float*)d_in[3];   // [3840, 256]
    const float* bf   = (const float*)d_in[4];   // [256]
    const int*   NAS  = (const int*)d_in[5];     // [6]
    float* out = (float*)d_out;                  // [32, 512, 256]

    cudaFuncSetAttribute(k_pair_mma,  cudaFuncAttributeMaxDynamicSharedMemorySize, SMEM_BYTES);
    cudaFuncSetAttribute(k_final_mma, cudaFuncAttributeMaxDynamicSharedMemorySize, SMEM_BYTES);

    prep_wp<<<dim3(K1 / 64, EMB / 64, PAIRS), 256>>>(Wp, NAS);
    prep_wf<<<dim3(KF / 64, EMB / 64), 256>>>(Wf, NAS);

    k_pair_mma<<<dim3(256, PAIRS), NTHREADS, SMEM_BYTES>>>(feat, bp, NAS);
    k_final_mma<<<256, NTHREADS, SMEM_BYTES>>>(bf, NAS, out);
}

// round 16
// speedup vs baseline: 1.4854x; 1.4854x over previous
#include <cuda_runtime.h>
#include <cuda_bf16.h>
#include <cstdint>

#define EMB    256
#define K1     512
#define PAIRS  15
#define M_TOT  16384
#define KF     3840            // PAIRS*EMB

__constant__ int c_i[PAIRS] = {0,0,0,0,0,1,1,1,1,2,2,2,3,3,4};
__constant__ int c_j[PAIRS] = {1,2,3,4,5,2,3,4,5,3,4,5,4,5,5};

// Scratch (device globals: allocation-guard safe)
__device__ __nv_bfloat16 g_Wphi[(size_t)PAIRS * EMB * K1];   // W_pair^T hi  [p][n][k]
__device__ __nv_bfloat16 g_Wplo[(size_t)PAIRS * EMB * K1];   // W_pair^T lo
__device__ __nv_bfloat16 g_Wfhi[(size_t)EMB * KF];           // W_final^T hi [n][k]
__device__ __nv_bfloat16 g_Wflo[(size_t)EMB * KF];           // W_final^T lo
__device__ __nv_bfloat16 g_Hhi[(size_t)PAIRS * M_TOT * EMB]; // h hi [p][m][d]
__device__ __nv_bfloat16 g_Hlo[(size_t)PAIRS * M_TOT * EMB]; // h lo

__device__ __forceinline__ bool pair_active(const int* __restrict__ NAS, int p) {
    const int i = c_i[p], j = c_j[p];
    const int ni = (i < 2) ? 1 : NAS[i];
    const int nj = (j < 2) ? 1 : NAS[j];
    return (ni != 0) && (nj != 0);
}

__device__ __forceinline__ float tanh_fast(float x) {
    float y; asm("tanh.approx.f32 %0, %1;" : "=f"(y) : "f"(x)); return y;
}
__device__ __forceinline__ uint32_t s2u(const void* p) {
    uint32_t a;
    asm("{ .reg .u64 t; cvta.to.shared.u64 t, %1; cvt.u32.u64 %0, t; }" : "=r"(a) : "l"(p));
    return a;
}
// pack (x,y) -> bf16x2 with x in low half (memory order [x,y])
__device__ __forceinline__ uint32_t packbf(float x, float y) {
    uint32_t r; asm("cvt.rn.bf16x2.f32 %0, %1, %2;" : "=r"(r) : "f"(y), "f"(x));
    return r;
}
// residual pair: lo = val - float(hi)
__device__ __forceinline__ uint32_t lopair(uint32_t hp, float x, float y) {
    float hx = __uint_as_float(hp << 16);
    float hy = __uint_as_float(hp & 0xffff0000u);
    return packbf(x - hx, y - hy);
}
__device__ __forceinline__ void ldsm4(uint32_t* r, uint32_t addr) {
    asm volatile("ldmatrix.sync.aligned.m8n8.x4.shared.b16 {%0,%1,%2,%3}, [%4];"
                 : "=r"(r[0]), "=r"(r[1]), "=r"(r[2]), "=r"(r[3]) : "r"(addr));
}
__device__ __forceinline__ void mma16816(float* d, const uint32_t* a, uint32_t b0, uint32_t b1) {
    asm volatile("mma.sync.aligned.m16n8k16.row.col.f32.bf16.bf16.f32 "
                 "{%0,%1,%2,%3}, {%4,%5,%6,%7}, {%8,%9}, {%0,%1,%2,%3};"
                 : "+f"(d[0]), "+f"(d[1]), "+f"(d[2]), "+f"(d[3])
                 : "r"(a[0]), "r"(a[1]), "r"(a[2]), "r"(a[3]), "r"(b0), "r"(b1));
}
__device__ __forceinline__ void cpa16(uint32_t dst, const void* src) {
    asm volatile("cp.async.cg.shared.global [%0], [%1], 16;" :: "r"(dst), "l"(src));
}
#define CP_COMMIT() asm volatile("cp.async.commit_group;" ::: "memory")
#define CP_WAIT0()  asm volatile("cp.async.wait_group 0;" ::: "memory")

// BK=32 stage: A(128x32) hi/lo = 8KB each, B(128x32) hi/lo = 8KB each -> 32KB
#define ST_A_HI 0
#define ST_A_LO 8192
#define ST_B_HI 16384
#define ST_B_LO 24576
#define STAGE   32768
#define SM_STG  1024
#define SMEM_BYTES (SM_STG + 2 * STAGE)   // 66560 -> 2 CTAs/SM

// 64B logical rows (32 bf16), two rows packed per 128B line, XOR-swizzled chunks.
// u = 16B chunk index within row (0..3)
__device__ __forceinline__ uint32_t swoff32(int row, int u) {
    int line  = row >> 1;
    int inner = (((row & 1) << 2) | u) ^ (line & 7);
    return (uint32_t)(line * 128 + inner * 16);
}

// ---------------- one BK=32 stage of split-bf16 MMA -------------------------
// 8 warps (4m x 2n), warp tile 32(m) x 64(n). acc[2][8][4]
__device__ __forceinline__ void stage_mma(uint32_t stb, int warp_m, int warp_n,
                                          int lane, float acc[2][8][4]) {
    const int l15 = lane & 15, lh = lane >> 4;
    #pragma unroll
    for (int kk = 0; kk < 2; kk++) {
        const int ch = kk * 2 + lh;   // 0..3
        uint32_t ah[2][4], al[2][4];
        #pragma unroll
        for (int mi = 0; mi < 2; mi++) {
            const int r = warp_m * 32 + mi * 16 + l15;
            const uint32_t o = swoff32(r, ch);
            ldsm4(ah[mi], stb + ST_A_HI + o);
            ldsm4(al[mi], stb + ST_A_LO + o);
        }
        #pragma unroll
        for (int ng = 0; ng < 4; ng++) {
            const int r = warp_n * 64 + ng * 16 + l15;
            const uint32_t o = swoff32(r, ch);
            uint32_t bh[4], bl[4];
            ldsm4(bh, stb + ST_B_HI + o);
            ldsm4(bl, stb + ST_B_LO + o);
            #pragma unroll
            for (int mi = 0; mi < 2; mi++) {
                mma16816(acc[mi][ng * 2 + 0], ah[mi], bh[0], bh[2]);
                mma16816(acc[mi][ng * 2 + 0], ah[mi], bl[0], bl[2]);
                mma16816(acc[mi][ng * 2 + 0], al[mi], bh[0], bh[2]);
                mma16816(acc[mi][ng * 2 + 1], ah[mi], bh[1], bh[3]);
                mma16816(acc[mi][ng * 2 + 1], ah[mi], bl[1], bl[3]);
                mma16816(acc[mi][ng * 2 + 1], al[mi], bh[1], bh[3]);
            }
        }
    }
}

// ---------------------------------------------------------------------------
// Prep: transpose + bf16-split weights
// ---------------------------------------------------------------------------
__global__ void prep_wp(const float* __restrict__ Wp, const int* __restrict__ NAS) {
    const int p = blockIdx.z;
    if (!pair_active(NAS, p)) return;
    __shared__ float t[64][65];
    const int k0 = blockIdx.x * 64, n0 = blockIdx.y * 64;
    const int tid = threadIdx.x;
    #pragma unroll
    for (int i = 0; i < 16; i++) {
        int idx = i * 256 + tid; int r = idx >> 6, c = idx & 63;
        t[r][c] = Wp[((size_t)p * K1 + k0 + r) * EMB + n0 + c];
    }
    __syncthreads();
    #pragma unroll
    for (int i = 0; i < 16; i++) {
        int idx = i * 256 + tid; int r = idx >> 6, c = idx & 63;
        float x = t[c][r];
        __nv_bfloat16 h = __float2bfloat16(x);
        size_t o = ((size_t)p * EMB + n0 + r) * K1 + k0 + c;
        g_Wphi[o] = h;
        g_Wplo[o] = __float2bfloat16(x - __bfloat162float(h));
    }
}
__global__ void prep_wf(const float* __restrict__ Wf, const int* __restrict__ NAS) {
    const int k0 = blockIdx.x * 64;
    if (!pair_active(NAS, k0 >> 8)) return;
    __shared__ float t[64][65];
    const int n0 = blockIdx.y * 64;
    const int tid = threadIdx.x;
    #pragma unroll
    for (int i = 0; i < 16; i++) {
        int idx = i * 256 + tid; int r = idx >> 6, c = idx & 63;
        t[r][c] = Wf[(size_t)(k0 + r) * EMB + n0 + c];
    }
    __syncthreads();
    #pragma unroll
    for (int i = 0; i < 16; i++) {
        int idx = i * 256 + tid; int r = idx >> 6, c = idx & 63;
        float x = t[c][r];
        __nv_bfloat16 h = __float2bfloat16(x);
        size_t o = (size_t)(n0 + r) * KF + k0 + c;
        g_Wfhi[o] = h;
        g_Wflo[o] = __float2bfloat16(x - __bfloat162float(h));
    }
}

// ---------------------------------------------------------------------------
// GEMM1: h[p] = tanh([f_i|f_j] @ W_p + b_p)   (HMMA, split-bf16 3-pass)
// grid: (128 Mtiles * 2 Ntiles, PAIRS), 256 threads, 2 CTAs/SM
// ---------------------------------------------------------------------------
__global__ __launch_bounds__(256, 2)
void k_pair_mma(const float* __restrict__ feat, const float* __restrict__ bp,
                const int* __restrict__ NAS)
{
    extern __shared__ char smem[];
    const int p = blockIdx.y;
    if (!pair_active(NAS, p)) return;
    const int tid = threadIdx.x, lane = tid & 31, wid = tid >> 5;
    const int warp_m = wid & 3, warp_n = wid >> 2;
    const int bm = (blockIdx.x >> 1) * 128, bn = (blockIdx.x & 1) * 128;
    const uint32_t sb = s2u(smem);
    float* bias_s = (float*)smem;
    if (tid < 32) ((float4*)bias_s)[tid] = ((const float4*)(bp + p * EMB + bn))[tid];

    const __nv_bfloat16* WH = g_Wphi + ((size_t)p * EMB + bn) * K1;
    const __nv_bfloat16* WL = g_Wplo + ((size_t)p * EMB + bn) * K1;

    float acc[2][8][4];
    #pragma unroll
    for (int a = 0; a < 2; a++)
        #pragma unroll
        for (int b = 0; b < 8; b++)
            #pragma unroll
            for (int c = 0; c < 4; c++) acc[a][b][c] = 0.f;

    const int NT = K1 / 32;   // 16
    float4 av[2][2];

    // B tile: 128 rows x 32 k = 512 chunk-tasks; 2 per thread
    auto issueB = [&](int t, int buf) {
        const int k0 = t * 32;
        #pragma unroll
        for (int it = 0; it < 2; it++) {
            int c = it * 256 + tid; int row = c >> 2, u = c & 3;
            uint32_t d = sb + SM_STG + buf * STAGE + swoff32(row, u);
            cpa16(d + ST_B_HI, WH + (size_t)row * K1 + k0 + u * 8);
            cpa16(d + ST_B_LO, WL + (size_t)row * K1 + k0 + u * 8);
        }
    };
    auto ldgA = [&](int t) {
        const int k0 = t * 32;
        const int f  = (k0 < EMB) ? c_i[p] : c_j[p];
        const float* A = feat + ((size_t)f * M_TOT + bm) * EMB + (k0 & (EMB - 1));
        #pragma unroll
        for (int it = 0; it < 2; it++) {
            int c = it * 256 + tid; int row = c >> 2, u = c & 3;
            av[it][0] = *reinterpret_cast<const float4*>(A + (size_t)row * EMB + u * 8);
            av[it][1] = *reinterpret_cast<const float4*>(A + (size_t)row * EMB + u * 8 + 4);
        }
    };
    auto stsA = [&](int buf) {
        #pragma unroll
        for (int it = 0; it < 2; it++) {
            int c = it * 256 + tid; int row = c >> 2, u = c & 3;
            uint4 hq, lq;
            hq.x = packbf(av[it][0].x, av[it][0].y); lq.x = lopair(hq.x, av[it][0].x, av[it][0].y);
            hq.y = packbf(av[it][0].z, av[it][0].w); lq.y = lopair(hq.y, av[it][0].z, av[it][0].w);
            hq.z = packbf(av[it][1].x, av[it][1].y); lq.z = lopair(hq.z, av[it][1].x, av[it][1].y);
            hq.w = packbf(av[it][1].z, av[it][1].w); lq.w = lopair(hq.w, av[it][1].z, av[it][1].w);
            char* base = smem + SM_STG + buf * STAGE + swoff32(row, u);
            *reinterpret_cast<uint4*>(base + ST_A_HI) = hq;
            *reinterpret_cast<uint4*>(base + ST_A_LO) = lq;
        }
    };

    // prologue
    issueB(0, 0); CP_COMMIT();
    ldgA(0); stsA(0);
    CP_WAIT0(); __syncthreads();

    for (int t = 0; t < NT; t++) {
        const int buf = t & 1;
        if (t + 1 < NT) { issueB(t + 1, buf ^ 1); CP_COMMIT(); ldgA(t + 1); }
        stage_mma(sb + SM_STG + buf * STAGE, warp_m, warp_n, lane, acc);
        if (t + 1 < NT) stsA(buf ^ 1);
        CP_WAIT0(); __syncthreads();
    }

    // epilogue: bias + tanh -> hi/lo bf16 in g_H
    const int r0 = lane >> 2, c2 = (lane & 3) * 2;
    #pragma unroll
    for (int mi = 0; mi < 2; mi++)
        #pragma unroll
        for (int hf = 0; hf < 2; hf++) {
            const int m = bm + warp_m * 32 + mi * 16 + r0 + hf * 8;
            const size_t rb = ((size_t)p * M_TOT + m) * EMB + bn + warp_n * 64;
            #pragma unroll
            for (int ni = 0; ni < 8; ni++) {
                const int col = ni * 8 + c2;
                float x0 = tanh_fast(acc[mi][ni][hf * 2 + 0] + bias_s[warp_n * 64 + col]);
                float x1 = tanh_fast(acc[mi][ni][hf * 2 + 1] + bias_s[warp_n * 64 + col + 1]);
                uint32_t hp = packbf(x0, x1);
                uint32_t lp = lopair(hp, x0, x1);
                *reinterpret_cast<uint32_t*>(g_Hhi + rb + col) = hp;
                *reinterpret_cast<uint32_t*>(g_Hlo + rb + col) = lp;
            }
        }
}

// ---------------------------------------------------------------------------
// GEMM2: out = h_flat @ W_final + b_final (active pairs only)
// grid: 128 Mtiles * 2 Ntiles = 256 CTAs -> single wave at 2 CTAs/SM
// ---------------------------------------------------------------------------
__global__ __launch_bounds__(256, 2)
void k_final_mma(const float* __restrict__ bf, const int* __restrict__ NAS,
                 float* __restrict__ out)
{
    extern __shared__ char smem[];
    const int tid = threadIdx.x, lane = tid & 31, wid = tid >> 5;
    const int warp_m = wid & 3, warp_n = wid >> 2;
    const int bm = (blockIdx.x >> 1) * 128, bn = (blockIdx.x & 1) * 128;
    const uint32_t sb = s2u(smem);
    float* bias_s = (float*)smem;
    if (tid < 32) ((float4*)bias_s)[tid] = ((const float4*)(bf + bn))[tid];

    int act[PAIRS]; int nact = 0;
    #pragma unroll
    for (int p = 0; p < PAIRS; p++)
        if (pair_active(NAS, p)) act[nact++] = p;
    const int NT = nact * 8;   // 8 k32-stages per active pair

    float acc[2][8][4];
    #pragma unroll
    for (int a = 0; a < 2; a++)
        #pragma unroll
        for (int b = 0; b < 8; b++)
            #pragma unroll
            for (int c = 0; c < 4; c++) acc[a][b][c] = 0.f;

    auto issue = [&](int t, int buf) {
        const int p  = act[t >> 3];
        const int k0 = (t & 7) * 32;
        const __nv_bfloat16* HH = g_Hhi + ((size_t)p * M_TOT + bm) * EMB + k0;
        const __nv_bfloat16* HL = g_Hlo + ((size_t)p * M_TOT + bm) * EMB + k0;
        const __nv_bfloat16* WH = g_Wfhi + (size_t)bn * KF + p * EMB + k0;
        const __nv_bfloat16* WL = g_Wflo + (size_t)bn * KF + p * EMB + k0;
        #pragma unroll
        for (int it = 0; it < 2; it++) {
            int c = it * 256 + tid; int row = c >> 2, u = c & 3;
            uint32_t d = sb + SM_STG + buf * STAGE + swoff32(row, u);
            cpa16(d + ST_A_HI, HH + (size_t)row * EMB + u * 8);
            cpa16(d + ST_A_LO, HL + (size_t)row * EMB + u * 8);
            cpa16(d + ST_B_HI, WH + (size_t)row * KF + u * 8);
            cpa16(d + ST_B_LO, WL + (size_t)row * KF + u * 8);
        }
    };

    issue(0, 0); CP_COMMIT();
    CP_WAIT0(); __syncthreads();

    for (int t = 0; t < NT; t++) {
        const int buf = t & 1;
        if (t + 1 < NT) { issue(t + 1, buf ^ 1); CP_COMMIT(); }
        stage_mma(sb + SM_STG + buf * STAGE, warp_m, warp_n, lane, acc);
        CP_WAIT0(); __syncthreads();
    }

    const int r0 = lane >> 2, c2 = (lane & 3) * 2;
    #pragma unroll
    for (int mi = 0; mi < 2; mi++)
        #pragma unroll
        for (int hf = 0; hf < 2; hf++) {
            const int m = bm + warp_m * 32 + mi * 16 + r0 + hf * 8;
            float* ob = out + (size_t)m * EMB + bn + warp_n * 64;
            #pragma unroll
            for (int ni = 0; ni < 8; ni++) {
                const int col = ni * 8 + c2;
                float2 v;
                v.x = acc[mi][ni][hf * 2 + 0] + bias_s[warp_n * 64 + col];
                v.y = acc[mi][ni][hf * 2 + 1] + bias_s[warp_n * 64 + col + 1];
                *reinterpret_cast<float2*>(ob + col) = v;
            }
        }
}

extern "C" void kernel_launch(void* const* d_in, const int* in_sizes, int n_in,
                              void* d_out, int out_size)
{
    const float* feat = (const float*)d_in[0];   // [6, 32, 512, 256]
    const float* Wp   = (const float*)d_in[1];   // [15, 512, 256]
    const float* bp   = (const float*)d_in[2];   // [15, 256]
    const float* Wf   = (const float*)d_in[3];   // [3840, 256]
    const float* bf   = (const float*)d_in[4];   // [256]
    const int*   NAS  = (const int*)d_in[5];     // [6]
    float* out = (float*)d_out;                  // [32, 512, 256]

    cudaFuncSetAttribute(k_pair_mma,  cudaFuncAttributeMaxDynamicSharedMemorySize, SMEM_BYTES);
    cudaFuncSetAttribute(k_final_mma, cudaFuncAttributeMaxDynamicSharedMemorySize, SMEM_BYTES);

    prep_wp<<<dim3(K1 / 64, EMB / 64, PAIRS), 256>>>(Wp, NAS);
    prep_wf<<<dim3(KF / 64, EMB / 64), 256>>>(Wf, NAS);

    k_pair_mma<<<dim3(256, PAIRS), 256, SMEM_BYTES>>>(feat, bp, NAS);
    k_final_mma<<<256, 256, SMEM_BYTES>>>(bf, NAS, out);
}